// round 11
// baseline (speedup 1.0000x reference)
#include <cuda_runtime.h>
#include <cuda_fp16.h>

#define N_NODES   100000
#define N_EDGES   1600000
#define N_TOT     1700000
#define N_GRAPHSX 2048
#define H         100
#define H4        25
#define K0        33
#define K0P       36
#define BN_EPS    1e-5f
#define NBLK_SCAN 98
#define WSL       (104 * 112)   // weight staging slice

// ---------------- scratch ----------------
__device__ __align__(16) __half g_xh[N_NODES * K0P];    // prescaled x (fp16)
__device__ __align__(16) __half g_hx[N_NODES * K0P];    // aggregated x (fp16)
__device__ __align__(16) __half g_h[N_NODES * H];       // h (fp16)
__device__ __align__(16) __half g_Y[N_NODES * H];       // Y = dis*(h@W) (fp16)
__device__ __align__(16) __half g_Wh[4 * WSL];          // transposed fp16 weights
__device__ __align__(16) float  g_bnS[4 * H];
__device__ __align__(16) float  g_bnT[4 * H];
__device__ float g_gsum[N_GRAPHSX];
__device__ float g_dis[N_NODES];
__device__ int   g_colptr[N_NODES + 1];
__device__ int   g_cursor[N_NODES];
__device__ int   g_csrsrc[N_TOT];
__device__ int   g_batch[N_NODES];
__device__ int   g_bsum[128];
__device__ int   g_boff[128];
__device__ int   g_is64;

// ---------------- init + probe ----------------
__global__ void k_init(const unsigned* __restrict__ ebuf) {
    int i = blockIdx.x * blockDim.x + threadIdx.x;
    if (i < N_NODES) g_cursor[i] = 1;
    if (i < N_GRAPHSX) g_gsum[i] = 0.f;
    if (i == 0) {
        int all0 = 1;
        for (int j = 1; j < 128; j += 2) all0 &= (ebuf[j] == 0u);
        g_is64 = all0;
    }
}

__global__ void k_count(const void* __restrict__ ebuf) {
    int e = blockIdx.x * blockDim.x + threadIdx.x;
    if (e >= N_EDGES) return;
    int d = g_is64 ? (int)((const long long*)ebuf)[N_EDGES + e]
                   : ((const int*)ebuf)[N_EDGES + e];
    atomicAdd(&g_cursor[d], 1);
}

__global__ void k_gptr(const void* __restrict__ bbuf) {
    int i = blockIdx.x * blockDim.x + threadIdx.x;
    if (i >= N_NODES) return;
    int b = g_is64 ? (int)((const long long*)bbuf)[i] : ((const int*)bbuf)[i];
    g_batch[i] = b;
}

// ---------------- scans ----------------
__global__ void k_scan_a() {
    __shared__ int red[256];
    int b = blockIdx.x, t = threadIdx.x;
    int base = b * 1024 + t * 4;
    int s = 0;
#pragma unroll
    for (int j = 0; j < 4; j++) {
        int idx = base + j;
        if (idx < N_NODES) {
            int c = g_cursor[idx];
            s += c;
            g_dis[idx] = rsqrtf((float)c);
        }
    }
    red[t] = s; __syncthreads();
    for (int off = 128; off > 0; off >>= 1) {
        if (t < off) red[t] += red[t + off];
        __syncthreads();
    }
    if (t == 0) g_bsum[b] = red[0];
}

__global__ void k_scan_b() {
    int lane = threadIdx.x;
    int base = lane * 4;
    int c[4]; int s = 0;
#pragma unroll
    for (int j = 0; j < 4; j++) {
        c[j] = (base + j < NBLK_SCAN) ? g_bsum[base + j] : 0;
        s += c[j];
    }
    int x = s;
#pragma unroll
    for (int off = 1; off < 32; off <<= 1) {
        int y = __shfl_up_sync(0xffffffffu, x, off);
        if (lane >= off) x += y;
    }
    int acc = x - s;
#pragma unroll
    for (int j = 0; j < 4; j++) {
        if (base + j < NBLK_SCAN) g_boff[base + j] = acc;
        acc += c[j];
    }
    if (lane == 31) g_colptr[N_NODES] = x;
}

__global__ void k_scan_c() {
    __shared__ int wsum[8], woff[8];
    int b = blockIdx.x, t = threadIdx.x;
    int base = b * 1024 + t * 4;
    int v[4];
#pragma unroll
    for (int j = 0; j < 4; j++) {
        int idx = base + j;
        v[j] = (idx < N_NODES) ? g_cursor[idx] : 0;
    }
    int s = v[0] + v[1] + v[2] + v[3];
    int lane = t & 31, w = t >> 5;
    int x = s;
#pragma unroll
    for (int off = 1; off < 32; off <<= 1) {
        int y = __shfl_up_sync(0xffffffffu, x, off);
        if (lane >= off) x += y;
    }
    if (lane == 31) wsum[w] = x;
    __syncthreads();
    if (t == 0) { int a = 0; for (int i = 0; i < 8; i++) { woff[i] = a; a += wsum[i]; } }
    __syncthreads();
    int excl = (x - s) + woff[w] + g_boff[b];
#pragma unroll
    for (int j = 0; j < 4; j++) {
        int idx = base + j;
        if (idx < N_NODES) {
            g_colptr[idx] = excl;
            g_csrsrc[excl] = idx;      // self loop
            g_cursor[idx] = excl + 1;
        }
        excl += v[j];
    }
}

__global__ void k_filledges(const void* __restrict__ ebuf) {
    int e = blockIdx.x * blockDim.x + threadIdx.x;
    if (e >= N_EDGES) return;
    int s, d;
    if (g_is64) {
        const long long* p = (const long long*)ebuf;
        s = (int)p[e]; d = (int)p[N_EDGES + e];
    } else {
        const int* p = (const int*)ebuf;
        s = p[e]; d = p[N_EDGES + e];
    }
    int pos = atomicAdd(&g_cursor[d], 1);
    g_csrsrc[pos] = s;
}

// ---------------- fused prep: BN consts + all weight transposes -----------
__global__ void k_prep(const float* __restrict__ W0, const float* __restrict__ Ws,
                       const float* __restrict__ bias, const float* __restrict__ gamma,
                       const float* __restrict__ beta, const float* __restrict__ mean,
                       const float* __restrict__ var) {
    int i = blockIdx.x * blockDim.x + threadIdx.x;
    if (i < 4 * H) {
        float s = gamma[i] * rsqrtf(var[i] + BN_EPS);
        g_bnS[i] = s;
        g_bnT[i] = (bias[i] - mean[i]) * s + beta[i];
        return;
    }
    int i0 = i - 4 * H;
    if (i0 < 104 * 48) {                     // layer 0: [104][48] <- W0[33][100]
        int n = i0 / 48, k = i0 % 48;
        g_Wh[i0] = (n < H && k < K0) ? __float2half(W0[k * H + n]) : __float2half(0.f);
        return;
    }
    int i1 = i0 - 104 * 48;
    if (i1 < 3 * WSL) {                      // layers 1-3: [104][112] <- Ws[l][100][100]
        int l = i1 / WSL, r = i1 % WSL;
        int n = r / 112, k = r % 112;
        g_Wh[WSL * (l + 1) + r] = (n < H && k < H)
            ? __float2half(Ws[l * H * H + k * H + n]) : __float2half(0.f);
    }
}

// ---------------- layer-0: prescale x by dis -> g_xh [N,36] fp16 ----------
__global__ void k_prescale(const float* __restrict__ x) {
    int i = blockIdx.x * blockDim.x + threadIdx.x;
    if (i >= N_NODES * K0P) return;
    int n = i / K0P, c = i % K0P;
    g_xh[i] = __float2half((c < K0) ? g_dis[n] * x[n * K0 + c] : 0.f);
}

// aggregate fp16 36-col rows: g_xh -> g_hx (warp/node, lanes 0..8, uint2)
__global__ void k_agg0() {
    int gwarp = (blockIdx.x * blockDim.x + threadIdx.x) >> 5;
    int lane = threadIdx.x & 31;
    if (gwarp >= N_NODES || lane >= 9) return;
    int n = gwarp;
    int beg = g_colptr[n], end = g_colptr[n + 1];
    const uint2* X2 = (const uint2*)g_xh;
    float ax = 0.f, ay = 0.f, az = 0.f, aw = 0.f;
    float bx = 0.f, by = 0.f, bz = 0.f, bw = 0.f;
    int i = beg;
    for (; i + 1 < end; i += 2) {
        int s0 = g_csrsrc[i], s1 = g_csrsrc[i + 1];
        uint2 u0 = X2[s0 * 9 + lane];
        uint2 u1 = X2[s1 * 9 + lane];
        float2 p;
        p = __half22float2(*(__half2*)&u0.x); ax += p.x; ay += p.y;
        p = __half22float2(*(__half2*)&u0.y); az += p.x; aw += p.y;
        p = __half22float2(*(__half2*)&u1.x); bx += p.x; by += p.y;
        p = __half22float2(*(__half2*)&u1.y); bz += p.x; bw += p.y;
    }
    if (i < end) {
        int s0 = g_csrsrc[i];
        uint2 u0 = X2[s0 * 9 + lane];
        float2 p;
        p = __half22float2(*(__half2*)&u0.x); ax += p.x; ay += p.y;
        p = __half22float2(*(__half2*)&u0.y); az += p.x; aw += p.y;
    }
    float d = g_dis[n];
    __half2 h0 = __floats2half2_rn((ax + bx) * d, (ay + by) * d);
    __half2 h1 = __floats2half2_rn((az + bz) * d, (aw + bw) * d);
    uint2 u; u.x = *(unsigned*)&h0; u.y = *(unsigned*)&h1;
    *(uint2*)&g_hx[n * K0P + lane * 4] = u;
}

// ---------------- MMA v3: BM=64, 256 thr, warps = 4 row-groups x 2 n-groups
// MODE 0: A=g_hx [N,36] -> g_h fp16, epi = BN(layer0)+ReLU
// MODE 1: A=g_h  [N,100] -> g_Y fp16, epi = *dis[row]
template <int KPAD, int KA, int MODE>
__global__ void __launch_bounds__(256) k_mma(const __half* __restrict__ Wp) {
    constexpr int KS = KPAD + 8;
    constexpr int C2 = KA / 2;
    constexpr int P2 = (KPAD - KA) / 2;
    extern __shared__ __half smem[];
    __half* As = smem;                 // [64][KS]
    __half* Bs = smem + 64 * KS;       // [104][KS]
    int row0 = blockIdx.x * 64;
    int tid = threadIdx.x;

    const __half* Asrc = (MODE == 0) ? g_hx : g_h;
    const __half2 z2 = __float2half2_rn(0.f);
    for (int i = tid; i < 64 * C2; i += 256) {
        int r = i / C2, c2 = i % C2;
        int gr = row0 + r;
        __half2 v = (gr < N_NODES) ? ((const __half2*)Asrc)[gr * C2 + c2] : z2;
        *(__half2*)&As[r * KS + c2 * 2] = v;
    }
    for (int i = tid; i < 64 * P2; i += 256) {
        int r = i / P2, j = i % P2;
        *(__half2*)&As[r * KS + KA + j * 2] = z2;
    }
    for (int i = tid; i < 104 * (KPAD / 2); i += 256) {
        int nn = i / (KPAD / 2), c2 = i % (KPAD / 2);
        __half2 v = ((const __half2*)Wp)[i];
        *(__half2*)&Bs[nn * KS + c2 * 2] = v;
    }
    __syncthreads();

    int warp = tid >> 5, lane = tid & 31;
    int g = lane >> 2, t = lane & 3;
    int r0 = (warp & 3) * 16;
    int ngrp = warp >> 2;
    int nbase = ngrp * 7;                    // tiles 0-6 / 7-12
    int jn = ngrp ? 6 : 7;
    float acc[7][4];
#pragma unroll
    for (int j = 0; j < 7; j++)
#pragma unroll
        for (int c = 0; c < 4; c++) acc[j][c] = 0.f;

#pragma unroll
    for (int ks = 0; ks < KPAD / 16; ks++) {
        int kb = ks * 16 + t * 2;
        unsigned a0 = *(unsigned*)&As[(r0 + g) * KS + kb];
        unsigned a1 = *(unsigned*)&As[(r0 + g + 8) * KS + kb];
        unsigned a2 = *(unsigned*)&As[(r0 + g) * KS + kb + 8];
        unsigned a3 = *(unsigned*)&As[(r0 + g + 8) * KS + kb + 8];
#pragma unroll
        for (int j = 0; j < 7; j++) {
            if (j >= jn) break;
            int nr = (nbase + j) * 8 + g;
            unsigned b0 = *(unsigned*)&Bs[nr * KS + kb];
            unsigned b1 = *(unsigned*)&Bs[nr * KS + kb + 8];
            asm volatile(
                "mma.sync.aligned.m16n8k16.row.col.f32.f16.f16.f32 "
                "{%0,%1,%2,%3}, {%4,%5,%6,%7}, {%8,%9}, {%0,%1,%2,%3};"
                : "+f"(acc[j][0]), "+f"(acc[j][1]), "+f"(acc[j][2]), "+f"(acc[j][3])
                : "r"(a0), "r"(a1), "r"(a2), "r"(a3), "r"(b0), "r"(b1));
        }
    }

    int gr0 = row0 + r0 + g;
    int gr1 = gr0 + 8;
    if (MODE == 0) {
#pragma unroll
        for (int j = 0; j < 7; j++) {
            if (j >= jn) break;
            int c = (nbase + j) * 8 + t * 2;
            if (c >= H) continue;
            float Sx = g_bnS[c], Sy = g_bnS[c + 1];
            float Tx = g_bnT[c], Ty = g_bnT[c + 1];
            if (gr0 < N_NODES) {
                float ox = fmaxf(fmaf(acc[j][0], Sx, Tx), 0.f);
                float oy = fmaxf(fmaf(acc[j][1], Sy, Ty), 0.f);
                __half2 hv = __floats2half2_rn(ox, oy);
                *(__half2*)&g_h[gr0 * H + c] = hv;
            }
            if (gr1 < N_NODES) {
                float ox = fmaxf(fmaf(acc[j][2], Sx, Tx), 0.f);
                float oy = fmaxf(fmaf(acc[j][3], Sy, Ty), 0.f);
                __half2 hv = __floats2half2_rn(ox, oy);
                *(__half2*)&g_h[gr1 * H + c] = hv;
            }
        }
    } else {
        float d0 = (gr0 < N_NODES) ? g_dis[gr0] : 0.f;
        float d1 = (gr1 < N_NODES) ? g_dis[gr1] : 0.f;
#pragma unroll
        for (int j = 0; j < 7; j++) {
            if (j >= jn) break;
            int c = (nbase + j) * 8 + t * 2;
            if (c >= H) continue;
            if (gr0 < N_NODES) {
                __half2 hv = __floats2half2_rn(acc[j][0] * d0, acc[j][1] * d0);
                *(__half2*)&g_Y[gr0 * H + c] = hv;
            }
            if (gr1 < N_NODES) {
                __half2 hv = __floats2half2_rn(acc[j][2] * d1, acc[j][3] * d1);
                *(__half2*)&g_Y[gr1 * H + c] = hv;
            }
        }
    }
}

// ---------------- aggregation: g_Y(fp16) -> g_h(fp16)  [LAST: fused pool] --
template <int LAST>
__global__ void k_agg(int layer, int relu, const float* __restrict__ hW) {
    int gwarp = (blockIdx.x * blockDim.x + threadIdx.x) >> 5;
    int lane = threadIdx.x & 31;
    if (gwarp >= N_NODES) return;
    int n = gwarp;
    float ox = 0.f, oy = 0.f, oz = 0.f, ow = 0.f;
    if (lane < H4) {
        int beg = g_colptr[n], end = g_colptr[n + 1];
        const uint2* Y2 = (const uint2*)g_Y;
        float a0x=0.f,a0y=0.f,a0z=0.f,a0w=0.f;
        float a1x=0.f,a1y=0.f,a1z=0.f,a1w=0.f;
        float a2x=0.f,a2y=0.f,a2z=0.f,a2w=0.f;
        float a3x=0.f,a3y=0.f,a3z=0.f,a3w=0.f;
        int i = beg;
        for (; i + 3 < end; i += 4) {
            int s0 = g_csrsrc[i], s1 = g_csrsrc[i+1], s2 = g_csrsrc[i+2], s3 = g_csrsrc[i+3];
            uint2 u0 = Y2[s0 * H4 + lane];
            uint2 u1 = Y2[s1 * H4 + lane];
            uint2 u2 = Y2[s2 * H4 + lane];
            uint2 u3 = Y2[s3 * H4 + lane];
            float2 p;
            p = __half22float2(*(__half2*)&u0.x); a0x += p.x; a0y += p.y;
            p = __half22float2(*(__half2*)&u0.y); a0z += p.x; a0w += p.y;
            p = __half22float2(*(__half2*)&u1.x); a1x += p.x; a1y += p.y;
            p = __half22float2(*(__half2*)&u1.y); a1z += p.x; a1w += p.y;
            p = __half22float2(*(__half2*)&u2.x); a2x += p.x; a2y += p.y;
            p = __half22float2(*(__half2*)&u2.y); a2z += p.x; a2w += p.y;
            p = __half22float2(*(__half2*)&u3.x); a3x += p.x; a3y += p.y;
            p = __half22float2(*(__half2*)&u3.y); a3z += p.x; a3w += p.y;
        }
        for (; i < end; i++) {
            int s0 = g_csrsrc[i];
            uint2 u0 = Y2[s0 * H4 + lane];
            float2 p;
            p = __half22float2(*(__half2*)&u0.x); a0x += p.x; a0y += p.y;
            p = __half22float2(*(__half2*)&u0.y); a0z += p.x; a0w += p.y;
        }
        float ax = (a0x + a1x) + (a2x + a3x);
        float ay = (a0y + a1y) + (a2y + a3y);
        float az = (a0z + a1z) + (a2z + a3z);
        float aw = (a0w + a1w) + (a2w + a3w);
        float d = g_dis[n];
        int c = layer * H + lane * 4;
        float4 S = *(const float4*)&g_bnS[c];
        float4 T = *(const float4*)&g_bnT[c];
        ox = fmaf(ax * d, S.x, T.x);
        oy = fmaf(ay * d, S.y, T.y);
        oz = fmaf(az * d, S.z, T.z);
        ow = fmaf(aw * d, S.w, T.w);
        if (relu) {
            ox = fmaxf(ox, 0.f); oy = fmaxf(oy, 0.f);
            oz = fmaxf(oz, 0.f); ow = fmaxf(ow, 0.f);
        }
    }
    if (LAST == 0) {
        if (lane < H4) {
            __half2 h0 = __floats2half2_rn(ox, oy);
            __half2 h1 = __floats2half2_rn(oz, ow);
            uint2 u; u.x = *(unsigned*)&h0; u.y = *(unsigned*)&h1;
            *(uint2*)&g_h[n * H + lane * 4] = u;
        }
    } else {
        float s = 0.f;
        if (lane < H4) {
            float4 w4 = ((const float4*)hW)[lane];
            s = ox * w4.x + oy * w4.y + oz * w4.z + ow * w4.w;
        }
#pragma unroll
        for (int off = 16; off > 0; off >>= 1)
            s += __shfl_down_sync(0xffffffffu, s, off);
        if (lane == 0) atomicAdd(&g_gsum[g_batch[n]], s);
    }
}

// ---------------- finish: bias + LeakyReLU ----------------
__global__ void k_finish(const float* __restrict__ hb, float* __restrict__ out) {
    int g = blockIdx.x * blockDim.x + threadIdx.x;
    if (g >= N_GRAPHSX) return;
    float o = g_gsum[g] + hb[0];
    out[g] = (o >= 0.f) ? o : 0.1f * o;
}

// ---------------- launch ----------------
extern "C" void kernel_launch(void* const* d_in, const int* in_sizes, int n_in,
                              void* d_out, int out_size) {
    const float* x      = (const float*)d_in[0];
    const void*  ei     = d_in[1];
    const void*  batch  = d_in[2];
    const float* W0     = (const float*)d_in[3];
    const float* Ws     = (const float*)d_in[4];
    const float* biases = (const float*)d_in[5];
    const float* gamma  = (const float*)d_in[6];
    const float* beta   = (const float*)d_in[7];
    const float* mean   = (const float*)d_in[8];
    const float* var    = (const float*)d_in[9];
    const float* headW  = (const float*)d_in[10];
    const float* headb  = (const float*)d_in[11];
    float* out = (float*)d_out;

    const int smem_big   = (64 + 104) * (112 + 8) * 2;  // 40320 (< 48KB default)
    const int smem_small = (64 + 104) * (48 + 8) * 2;   // 18816

    __half* whp = nullptr;
    cudaGetSymbolAddress((void**)&whp, g_Wh);

    k_init<<<(N_NODES + 255) / 256, 256>>>((const unsigned*)ei);
    k_count<<<(N_EDGES + 255) / 256, 256>>>(ei);
    k_gptr<<<(N_NODES + 255) / 256, 256>>>(batch);
    k_scan_a<<<NBLK_SCAN, 256>>>();
    k_scan_b<<<1, 32>>>();
    k_scan_c<<<NBLK_SCAN, 256>>>();
    k_filledges<<<(N_EDGES + 255) / 256, 256>>>(ei);
    k_prep<<<(4 * H + 104 * 48 + 3 * WSL + 255) / 256, 256>>>(W0, Ws, biases, gamma, beta, mean, var);

    int mma_blocks = (N_NODES + 63) / 64;
    int agg_blocks = (N_NODES * 32 + 255) / 256;

    // layer 0: prescale(fp16) -> aggregate -> MMA (BN0+ReLU)
    k_prescale<<<(N_NODES * K0P + 255) / 256, 256>>>(x);
    k_agg0<<<agg_blocks, 256>>>();
    k_mma<48, 36, 0><<<mma_blocks, 256, smem_small>>>(whp);
    // layers 1..3
    for (int l = 1; l < 4; l++) {
        k_mma<112, 100, 1><<<mma_blocks, 256, smem_big>>>(whp + l * WSL);
        if (l < 3) k_agg<0><<<agg_blocks, 256>>>(l, 1, headW);
        else       k_agg<1><<<agg_blocks, 256>>>(l, 0, headW);
    }

    k_finish<<<(N_GRAPHSX + 255) / 256, 256>>>(headb, out);
}